// round 12
// baseline (speedup 1.0000x reference)
#include <cuda_runtime.h>

// YoloLoss: N=4096, S=14, B=2, NUM_CLS=20.
// All-float4 streaming: pred + tcls loaded as LDG.128 (halves LDG/issue
// pressure vs float2), box channels staged in stride-31 smem.
// Tail: 5 pre-scaled fire-and-forget REDs into d_out; graph memset node
// zeroes d_out each replay. NO gpu-scope fences (measured +15us L1-flush
// penalty R3/R5/R7).
// inputs: pred_tensor (N,S,S,30) f32, target_boxes (N,S,S,4) f32,
//         target_cls (N,S,S,20) f32, has_object_map (N,S,S) int32
// output: 5 f32 = (total, reg, contain_conf, no_obj, cls)

static constexpr int NSAMP = 4096;
static constexpr int S2    = 14 * 14;
static constexpr int NCELL = NSAMP * S2;   // 802816
static constexpr int CPB   = 128;          // cells (== threads) per block
static constexpr int NBLK  = NCELL / CPB;  // 6272

__global__ __launch_bounds__(CPB, 13) void yolo_k(
    const float* __restrict__ pred,
    const float* __restrict__ tbox,
    const float* __restrict__ tcls,
    const int* __restrict__ mask,
    float* __restrict__ out)
{
    // all 30 pred channels staged: stride 31 (odd -> conflict-free reads)
    __shared__ float sp[CPB * 31];      // 15872 B
    __shared__ float smask[CPB];
    __shared__ float red[CPB / 32][4];

    const int tid = threadIdx.x;
    const long base = (long)blockIdx.x * CPB;

    smask[tid] = (mask[base + tid] != 0) ? 1.0f : 0.0f;

    // --- stage pred via float4: 960 per block, 7.5/thread (last predicated).
    //     e = idx4*4 -> ch even; only ch==28 straddles a cell boundary.
    const float4* __restrict__ pg4 =
        reinterpret_cast<const float4*>(pred + base * 30);
#pragma unroll
    for (int i = 0; i < 8; i++) {
        if (i < 7 || tid < 64) {
            int idx4 = tid + i * CPB;       // 0..959
            float4 v = pg4[idx4];
            int e    = idx4 * 4;
            int cell = e / 30;
            int ch   = e - cell * 30;       // even
            if (ch <= 26) {
                float* d = &sp[cell * 31 + ch];
                d[0] = v.x; d[1] = v.y; d[2] = v.z; d[3] = v.w;
            } else {                        // ch == 28: split 2/2
                float* d0 = &sp[cell * 31 + 28];
                d0[0] = v.x; d0[1] = v.y;
                float* d1 = &sp[(cell + 1) * 31];
                d1[0] = v.z; d1[1] = v.w;
            }
        }
    }
    __syncthreads();

    // --- cls loss: float4-streamed tcls (20%4==0: never splits a cell) ---
    const float4* __restrict__ cg4 =
        reinterpret_cast<const float4*>(tcls + base * 20);
    float cls = 0.0f;
#pragma unroll
    for (int i = 0; i < 5; i++) {
        int idx4 = tid + i * CPB;       // 0..639
        float4 v = cg4[idx4];
        int e    = idx4 * 4;
        int cell = e / 20;
        int ch   = e - cell * 20;       // in {0,4,8,12,16}
        const float* p = &sp[cell * 31 + 10 + ch];
        float d0 = p[0] - v.x, d1 = p[1] - v.y;
        float d2 = p[2] - v.z, d3 = p[3] - v.w;
        cls += (d0 * d0 + d1 * d1 + d2 * d2 + d3 * d3) * smask[cell];
    }

    // --- per-cell box terms ---
    const float4 tb = reinterpret_cast<const float4*>(tbox)[base + tid];
    const float  m  = smask[tid];
    const float* P  = &sp[tid * 31];

    float c0 = P[4], c1 = P[9];
    float noobj = (c0 * c0 + c1 * c1) * (1.0f - m);   // 0.5 applied pre-RED

    const float invS = 1.0f / 14.0f;
    float gx1 = tb.x * invS - 0.5f * tb.z, gx2 = tb.x * invS + 0.5f * tb.z;
    float gy1 = tb.y * invS - 0.5f * tb.w, gy2 = tb.y * invS + 0.5f * tb.w;
    float area_g = (gx2 - gx1) * (gy2 - gy1);

    float iou0, iou1;
#pragma unroll
    for (int b = 0; b < 2; b++) {
        float px = P[5 * b + 0], py = P[5 * b + 1];
        float pw = P[5 * b + 2], ph = P[5 * b + 3];
        float px1 = px * invS - 0.5f * pw, px2 = px * invS + 0.5f * pw;
        float py1 = py * invS - 0.5f * ph, py2 = py * invS + 0.5f * ph;
        float iw = fmaxf(fminf(px2, gx2) - fmaxf(px1, gx1), 0.0f);
        float ih = fmaxf(fminf(py2, gy2) - fmaxf(py1, gy1), 0.0f);
        float inter  = iw * ih;
        float area_p = (px2 - px1) * (py2 - py1);
        float v = inter / (area_p + area_g - inter);
        if (b == 0) iou0 = v; else iou1 = v;
    }
    // jnp.argmax keeps first max on ties -> strict '>' for box 1
    const int best = (iou1 > iou0) ? 1 : 0;
    const float bx = P[5 * best + 0], by = P[5 * best + 1];
    const float bw = P[5 * best + 2], bh = P[5 * best + 3];
    const float bc = P[5 * best + 4];

    float dx = bx - tb.x, dy = by - tb.y;
    float dw = sqrtf(bw) - sqrtf(tb.z);
    float dh = sqrtf(bh) - sqrtf(tb.w);
    float regp = (dx * dx + dy * dy + dw * dw + dh * dh) * m;
    float dc = bc - 1.0f;
    float contain = dc * dc * m;

    // --- reduction: warp shuffle -> smem -> 5 pre-scaled REDs into d_out ---
    float v0 = regp, v1 = contain, v2 = noobj, v3 = cls;
#pragma unroll
    for (int off = 16; off > 0; off >>= 1) {
        v0 += __shfl_xor_sync(0xffffffffu, v0, off);
        v1 += __shfl_xor_sync(0xffffffffu, v1, off);
        v2 += __shfl_xor_sync(0xffffffffu, v2, off);
        v3 += __shfl_xor_sync(0xffffffffu, v3, off);
    }
    const int warp = tid >> 5;
    if ((tid & 31) == 0) {
        red[warp][0] = v0; red[warp][1] = v1;
        red[warp][2] = v2; red[warp][3] = v3;
    }
    __syncthreads();
    if (tid < 5) {
        float s0 = red[0][0] + red[1][0] + red[2][0] + red[3][0]; // reg raw
        float s1 = red[0][1] + red[1][1] + red[2][1] + red[3][1]; // contain
        float s2 = red[0][2] + red[1][2] + red[2][2] + red[3][2]; // noobj raw
        float s3 = red[0][3] + red[1][3] + red[2][3] + red[3][3]; // cls
        const float invN = 1.0f / (float)NSAMP;
        float val;
        switch (tid) {
            case 0: val = (5.0f * s0 + s1 + 0.5f * s2 + s3) * invN; break;
            case 1: val = 5.0f * s0 * invN; break;
            case 2: val = s1 * invN; break;
            case 3: val = 0.5f * s2 * invN; break;
            default: val = s3 * invN; break;
        }
        atomicAdd(&out[tid], val);   // return unused -> RED, no ordering op
    }
}

extern "C" void kernel_launch(void* const* d_in, const int* in_sizes, int n_in,
                              void* d_out, int out_size)
{
    const float* pred = (const float*)d_in[0];
    const float* tbox = (const float*)d_in[1];
    const float* tcls = (const float*)d_in[2];
    const int*   mask = (const int*)d_in[3];
    float* out = (float*)d_out;

    // graph memset node: zero the 5 output floats each replay (REDs add onto it)
    cudaMemsetAsync(out, 0, 5 * sizeof(float), 0);
    yolo_k<<<NBLK, CPB>>>(pred, tbox, tcls, mask, out);
}

// round 13
// speedup vs baseline: 1.1261x; 1.1261x over previous
#include <cuda_runtime.h>
#include <cstdint>

// YoloLoss: N=4096, S=14, B=2, NUM_CLS=20.
// TMA-staged: one thread per block issues 4 cp.async.bulk copies (pred,
// tcls, tbox, mask -> raw smem, 28160 B total) against one mbarrier.
// 28KB in flight per block from a single issue stream (~220KB/SM at 8
// blocks) breaks the ~5.5TB/s LDG MLP plateau. Compute reads raw smem.
// Tail: 5 pre-scaled fire-and-forget REDs into d_out; graph memset node
// zeroes d_out each replay. NO gpu-scope fences (R3/R5/R7: +15us).
// inputs: pred (N,S,S,30) f32, tbox (N,S,S,4) f32, tcls (N,S,S,20) f32,
//         mask (N,S,S) int32;  output: 5 f32.

static constexpr int NSAMP = 4096;
static constexpr int S2    = 14 * 14;
static constexpr int NCELL = NSAMP * S2;   // 802816
static constexpr int CPB   = 128;          // cells (== threads) per block
static constexpr int NBLK  = NCELL / CPB;  // 6272

static constexpr uint32_t PRED_B = CPB * 30 * 4;  // 15360
static constexpr uint32_t TCLS_B = CPB * 20 * 4;  // 10240
static constexpr uint32_t TBOX_B = CPB * 4 * 4;   //  2048
static constexpr uint32_t MASK_B = CPB * 4;       //   512
static constexpr uint32_t TOT_B  = PRED_B + TCLS_B + TBOX_B + MASK_B; // 28160

__device__ __forceinline__ uint32_t s2u(const void* p) {
    uint32_t a;
    asm("{ .reg .u64 t; cvta.to.shared.u64 t, %1; cvt.u32.u64 %0, t; }"
        : "=r"(a) : "l"(p));
    return a;
}

__global__ __launch_bounds__(CPB) void yolo_k(
    const float* __restrict__ pred,
    const float* __restrict__ tbox,
    const float* __restrict__ tcls,
    const int* __restrict__ mask,
    float* __restrict__ out)
{
    __shared__ alignas(16) float spred[CPB * 30];   // raw slab
    __shared__ alignas(16) float stcls[CPB * 20];   // raw slab
    __shared__ alignas(16) float4 stbox[CPB];
    __shared__ alignas(16) int   smsk[CPB];
    __shared__ float red[CPB / 32][4];
    __shared__ alignas(8) unsigned long long mbar;

    const int tid = threadIdx.x;
    const long base = (long)blockIdx.x * CPB;
    const uint32_t mb = s2u(&mbar);

    if (tid == 0) {
        asm volatile("mbarrier.init.shared.b64 [%0], %1;"
                     :: "r"(mb), "r"(1u) : "memory");
    }
    __syncthreads();

    if (tid == 0) {
        asm volatile("mbarrier.arrive.expect_tx.shared.b64 _, [%0], %1;"
                     :: "r"(mb), "r"(TOT_B) : "memory");
        asm volatile(
            "cp.async.bulk.shared::cta.global.mbarrier::complete_tx::bytes "
            "[%0], [%1], %2, [%3];"
            :: "r"(s2u(spred)), "l"(pred + base * 30), "r"(PRED_B), "r"(mb)
            : "memory");
        asm volatile(
            "cp.async.bulk.shared::cta.global.mbarrier::complete_tx::bytes "
            "[%0], [%1], %2, [%3];"
            :: "r"(s2u(stcls)), "l"(tcls + base * 20), "r"(TCLS_B), "r"(mb)
            : "memory");
        asm volatile(
            "cp.async.bulk.shared::cta.global.mbarrier::complete_tx::bytes "
            "[%0], [%1], %2, [%3];"
            :: "r"(s2u(stbox)), "l"(tbox + base * 4), "r"(TBOX_B), "r"(mb)
            : "memory");
        asm volatile(
            "cp.async.bulk.shared::cta.global.mbarrier::complete_tx::bytes "
            "[%0], [%1], %2, [%3];"
            :: "r"(s2u(smsk)), "l"(mask + base), "r"(MASK_B), "r"(mb)
            : "memory");
    }

    // all threads wait for phase 0 completion (acquire -> orders LDS after)
    {
        uint32_t done;
        do {
            asm volatile(
                "{\n\t.reg .pred p;\n\t"
                "mbarrier.try_wait.parity.acquire.cta.shared::cta.b64 p, [%1], %2, 0x989680;\n\t"
                "selp.b32 %0, 1, 0, p;\n\t}"
                : "=r"(done) : "r"(mb), "r"(0u) : "memory");
        } while (!done);
    }

    // ---------------- compute straight from raw smem ----------------
    const float2* Pb = reinterpret_cast<const float2*>(spred) + tid * 15;
    const float4* Tc = reinterpret_cast<const float4*>(stcls) + tid * 5;
    const float4  tb = stbox[tid];
    const float   m  = (smsk[tid] != 0) ? 1.0f : 0.0f;

    // box channels 0..9 as 5 float2 (stride 120B -> conflict-free)
    float2 p01 = Pb[0], p23 = Pb[1], p45 = Pb[2], p67 = Pb[3], p89 = Pb[4];

    // cls: pred pairs Pb[5..14] vs tcls float4s (stride 80B -> conflict-free)
    float cls = 0.0f;
#pragma unroll
    for (int q = 0; q < 5; q++) {
        float4 t = Tc[q];
        float2 a = Pb[5 + 2 * q];
        float2 b = Pb[6 + 2 * q];
        float d0 = a.x - t.x, d1 = a.y - t.y;
        float d2 = b.x - t.z, d3 = b.y - t.w;
        cls += d0 * d0 + d1 * d1 + d2 * d2 + d3 * d3;
    }
    cls *= m;

    // box0: x=p01.x y=p01.y w=p23.x h=p23.y conf=p45.x
    // box1: x=p45.y y=p67.x w=p67.y h=p89.x conf=p89.y
    float noobj = (p45.x * p45.x + p89.y * p89.y) * (1.0f - m);

    const float invS = 1.0f / 14.0f;
    float gx1 = tb.x * invS - 0.5f * tb.z, gx2 = tb.x * invS + 0.5f * tb.z;
    float gy1 = tb.y * invS - 0.5f * tb.w, gy2 = tb.y * invS + 0.5f * tb.w;
    float area_g = (gx2 - gx1) * (gy2 - gy1);

    float bxv[2] = {p01.x, p45.y};
    float byv[2] = {p01.y, p67.x};
    float bwv[2] = {p23.x, p67.y};
    float bhv[2] = {p23.y, p89.x};
    float bcv[2] = {p45.x, p89.y};

    float iou0, iou1;
#pragma unroll
    for (int b = 0; b < 2; b++) {
        float px1 = bxv[b] * invS - 0.5f * bwv[b];
        float px2 = bxv[b] * invS + 0.5f * bwv[b];
        float py1 = byv[b] * invS - 0.5f * bhv[b];
        float py2 = byv[b] * invS + 0.5f * bhv[b];
        float iw = fmaxf(fminf(px2, gx2) - fmaxf(px1, gx1), 0.0f);
        float ih = fmaxf(fminf(py2, gy2) - fmaxf(py1, gy1), 0.0f);
        float inter  = iw * ih;
        float area_p = (px2 - px1) * (py2 - py1);
        float v = inter / (area_p + area_g - inter);
        if (b == 0) iou0 = v; else iou1 = v;
    }
    // jnp.argmax keeps first max on ties -> strict '>' for box 1
    const bool sel1 = (iou1 > iou0);
    const float bx = sel1 ? bxv[1] : bxv[0];
    const float by = sel1 ? byv[1] : byv[0];
    const float bw = sel1 ? bwv[1] : bwv[0];
    const float bh = sel1 ? bhv[1] : bhv[0];
    const float bc = sel1 ? bcv[1] : bcv[0];

    float dx = bx - tb.x, dy = by - tb.y;
    float dw = sqrtf(bw) - sqrtf(tb.z);
    float dh = sqrtf(bh) - sqrtf(tb.w);
    float regp = (dx * dx + dy * dy + dw * dw + dh * dh) * m;
    float dc = bc - 1.0f;
    float contain = dc * dc * m;

    // --- reduction: warp shuffle -> smem -> 5 pre-scaled REDs into d_out ---
    float v0 = regp, v1 = contain, v2 = noobj, v3 = cls;
#pragma unroll
    for (int off = 16; off > 0; off >>= 1) {
        v0 += __shfl_xor_sync(0xffffffffu, v0, off);
        v1 += __shfl_xor_sync(0xffffffffu, v1, off);
        v2 += __shfl_xor_sync(0xffffffffu, v2, off);
        v3 += __shfl_xor_sync(0xffffffffu, v3, off);
    }
    const int warp = tid >> 5;
    if ((tid & 31) == 0) {
        red[warp][0] = v0; red[warp][1] = v1;
        red[warp][2] = v2; red[warp][3] = v3;
    }
    __syncthreads();
    if (tid < 5) {
        float s0 = red[0][0] + red[1][0] + red[2][0] + red[3][0]; // reg raw
        float s1 = red[0][1] + red[1][1] + red[2][1] + red[3][1]; // contain
        float s2 = red[0][2] + red[1][2] + red[2][2] + red[3][2]; // noobj raw
        float s3 = red[0][3] + red[1][3] + red[2][3] + red[3][3]; // cls
        const float invN = 1.0f / (float)NSAMP;
        float val;
        switch (tid) {
            case 0: val = (5.0f * s0 + s1 + 0.5f * s2 + s3) * invN; break;
            case 1: val = 5.0f * s0 * invN; break;
            case 2: val = s1 * invN; break;
            case 3: val = 0.5f * s2 * invN; break;
            default: val = s3 * invN; break;
        }
        atomicAdd(&out[tid], val);   // return unused -> RED, no ordering op
    }
}

extern "C" void kernel_launch(void* const* d_in, const int* in_sizes, int n_in,
                              void* d_out, int out_size)
{
    const float* pred = (const float*)d_in[0];
    const float* tbox = (const float*)d_in[1];
    const float* tcls = (const float*)d_in[2];
    const int*   mask = (const int*)d_in[3];
    float* out = (float*)d_out;

    // graph memset node: zero the 5 output floats each replay (REDs add onto it)
    cudaMemsetAsync(out, 0, 5 * sizeof(float), 0);
    yolo_k<<<NBLK, CPB>>>(pred, tbox, tcls, mask, out);
}